// round 3
// baseline (speedup 1.0000x reference)
#include <cuda_runtime.h>
#include <math.h>

#define NN 50000
#define FF 128
#define NE 800000
#define NT 5000
#define NCHUNK 49   // ceil(NN/1024)

// ---------------- static device scratch (no allocations allowed) ----------------
static __device__ float g_Me[NN * FF];   // sigmoid-gated M (train rows = 1)
static __device__ float g_Mx[NN * FF];   // M_eff * x
static __device__ float g_Hn[NN * FF];   // normalized H (pre-GEMM)
static __device__ int   g_cnt[NN];
static __device__ int   g_off[NN + 1];
static __device__ int   g_cur[NN];
static __device__ int   g_colS[NE];
static __device__ float g_valS[NE];
static __device__ int   g_bsum[NCHUNK];
static __device__ int   g_mask[NN];

// ---------------- small helpers ----------------
__device__ __forceinline__ float sigmoid_fast(float z) {
    return 1.0f / (1.0f + __expf(-z));
}
__device__ __forceinline__ float elu1(float v) {
    return v > 0.0f ? v : expm1f(v);
}

// ---------------- kernels ----------------
__global__ void k_zero() {
    int i = blockIdx.x * blockDim.x + threadIdx.x;
    if (i < NN) { g_cnt[i] = 0; g_mask[i] = 0; }
}

__global__ void k_mask(const int* __restrict__ tid) {
    int i = blockIdx.x * blockDim.x + threadIdx.x;
    if (i < NT) g_mask[tid[i]] = 1;
}

// M_eff = train ? 1 : sigmoid(M);  Mx = M_eff * x   (float4 vectorized)
__global__ void k_meff(const float* __restrict__ x, const float* __restrict__ M) {
    int i = blockIdx.x * blockDim.x + threadIdx.x;   // float4 index
    if (i >= NN * FF / 4) return;
    int node = i >> 5;                               // (i*4)/128
    float4 m  = ((const float4*)M)[i];
    float4 xv = ((const float4*)x)[i];
    float4 me, mx;
    if (g_mask[node]) {
        me = make_float4(1.f, 1.f, 1.f, 1.f);
        mx = xv;
    } else {
        me.x = sigmoid_fast(m.x); me.y = sigmoid_fast(m.y);
        me.z = sigmoid_fast(m.z); me.w = sigmoid_fast(m.w);
        mx.x = me.x * xv.x; mx.y = me.y * xv.y;
        mx.z = me.z * xv.z; mx.w = me.w * xv.w;
    }
    ((float4*)g_Me)[i] = me;
    ((float4*)g_Mx)[i] = mx;
}

__global__ void k_hist(const int* __restrict__ erow) {
    int e = blockIdx.x * blockDim.x + threadIdx.x;
    if (e < NE) atomicAdd(&g_cnt[erow[e]], 1);
}

// per-chunk exclusive scan (1024-wide Hillis-Steele)
__global__ void k_scan1() {
    __shared__ int sh[1024];
    int t = threadIdx.x, b = blockIdx.x;
    int i = b * 1024 + t;
    int v = (i < NN) ? g_cnt[i] : 0;
    sh[t] = v;
    __syncthreads();
    for (int ofs = 1; ofs < 1024; ofs <<= 1) {
        int add = (t >= ofs) ? sh[t - ofs] : 0;
        __syncthreads();
        sh[t] += add;
        __syncthreads();
    }
    if (i < NN) g_off[i] = sh[t] - v;     // chunk-local exclusive
    if (t == 1023) g_bsum[b] = sh[1023];  // chunk total
}

__global__ void k_scan2() {
    if (threadIdx.x == 0 && blockIdx.x == 0) {
        int acc = 0;
        for (int b = 0; b < NCHUNK; b++) {
            int v = g_bsum[b];
            g_bsum[b] = acc;
            acc += v;
        }
    }
}

__global__ void k_scan3() {
    int i = blockIdx.x * blockDim.x + threadIdx.x;
    if (i < NN) {
        int v = g_off[i] + g_bsum[i >> 10];
        g_off[i] = v;
        g_cur[i] = v;
    }
    if (i == 0) g_off[NN] = NE;
}

__global__ void k_scatter(const int* __restrict__ erow, const int* __restrict__ ecol,
                          const float* __restrict__ aval) {
    int e = blockIdx.x * blockDim.x + threadIdx.x;
    if (e >= NE) return;
    int r = erow[e];
    int p = atomicAdd(&g_cur[r], 1);
    g_colS[p] = ecol[e];
    g_valS[p] = aval[e];
}

// warp-per-row gather-reduce, 4-edge unrolled for MLP:
// denom += Me[col], h += w*Mx[col]; Hn = h / denom (0 if denom==0)
__global__ void k_gather() {
    int gt   = blockIdx.x * blockDim.x + threadIdx.x;
    int row  = gt >> 5;
    int lane = gt & 31;
    if (row >= NN) return;
    int s = g_off[row], e = g_off[row + 1];
    int base = lane * 4;
    float4 d = make_float4(0.f, 0.f, 0.f, 0.f);
    float4 h = make_float4(0.f, 0.f, 0.f, 0.f);
    int j = s;
    for (; j + 3 < e; j += 4) {
        int   c0 = __ldg(&g_colS[j]);
        int   c1 = __ldg(&g_colS[j + 1]);
        int   c2 = __ldg(&g_colS[j + 2]);
        int   c3 = __ldg(&g_colS[j + 3]);
        float w0 = __ldg(&g_valS[j]);
        float w1 = __ldg(&g_valS[j + 1]);
        float w2 = __ldg(&g_valS[j + 2]);
        float w3 = __ldg(&g_valS[j + 3]);
        float4 me0 = *(const float4*)&g_Me[c0 * FF + base];
        float4 me1 = *(const float4*)&g_Me[c1 * FF + base];
        float4 me2 = *(const float4*)&g_Me[c2 * FF + base];
        float4 me3 = *(const float4*)&g_Me[c3 * FF + base];
        float4 mx0 = *(const float4*)&g_Mx[c0 * FF + base];
        float4 mx1 = *(const float4*)&g_Mx[c1 * FF + base];
        float4 mx2 = *(const float4*)&g_Mx[c2 * FF + base];
        float4 mx3 = *(const float4*)&g_Mx[c3 * FF + base];
        d.x += (me0.x + me1.x) + (me2.x + me3.x);
        d.y += (me0.y + me1.y) + (me2.y + me3.y);
        d.z += (me0.z + me1.z) + (me2.z + me3.z);
        d.w += (me0.w + me1.w) + (me2.w + me3.w);
        h.x += (w0 * mx0.x + w1 * mx1.x) + (w2 * mx2.x + w3 * mx3.x);
        h.y += (w0 * mx0.y + w1 * mx1.y) + (w2 * mx2.y + w3 * mx3.y);
        h.z += (w0 * mx0.z + w1 * mx1.z) + (w2 * mx2.z + w3 * mx3.z);
        h.w += (w0 * mx0.w + w1 * mx1.w) + (w2 * mx2.w + w3 * mx3.w);
    }
    for (; j < e; ++j) {
        int   c = __ldg(&g_colS[j]);
        float w = __ldg(&g_valS[j]);
        float4 me = *(const float4*)&g_Me[c * FF + base];
        float4 mx = *(const float4*)&g_Mx[c * FF + base];
        d.x += me.x; d.y += me.y; d.z += me.z; d.w += me.w;
        h.x += w * mx.x; h.y += w * mx.y; h.z += w * mx.z; h.w += w * mx.w;
    }
    float4 o;
    o.x = (d.x != 0.f) ? h.x * __fdividef(1.f, d.x) : 0.f;
    o.y = (d.y != 0.f) ? h.y * __fdividef(1.f, d.y) : 0.f;
    o.z = (d.z != 0.f) ? h.z * __fdividef(1.f, d.z) : 0.f;
    o.w = (d.w != 0.f) ? h.w * __fdividef(1.f, d.w) : 0.f;
    *(float4*)&g_Hn[row * FF + base] = o;
}

// out = elu(Hn @ W).  Block: 256 threads, 32 rows x 128 cols tile.
// tx = t&31 -> column quad (cols 4tx..4tx+3); ty = t>>5 -> rows {ty, ty+8, ty+16, ty+24}
__global__ void k_gemm(const float* __restrict__ W, float* __restrict__ out) {
    __shared__ float Hs[32][FF];
    int r0 = blockIdx.x * 32;
    int t  = threadIdx.x;

    // cooperative load of 32 Hn rows
    for (int i = t; i < 32 * FF / 4; i += 256) {
        int row  = (i * 4) / FF;
        int colf = (i * 4) % FF;
        float4 v = (r0 + row < NN) ? *(const float4*)&g_Hn[(r0 + row) * FF + colf]
                                   : make_float4(0.f, 0.f, 0.f, 0.f);
        *(float4*)&Hs[row][colf] = v;
    }
    __syncthreads();

    int tx = t & 31;
    int ty = t >> 5;
    float acc[4][4];
    #pragma unroll
    for (int a = 0; a < 4; a++)
        #pragma unroll
        for (int b = 0; b < 4; b++) acc[a][b] = 0.f;

    #pragma unroll 4
    for (int f = 0; f < FF; f += 4) {
        float4 w0 = *(const float4*)&W[(f + 0) * FF + tx * 4];
        float4 w1 = *(const float4*)&W[(f + 1) * FF + tx * 4];
        float4 w2 = *(const float4*)&W[(f + 2) * FF + tx * 4];
        float4 w3 = *(const float4*)&W[(f + 3) * FF + tx * 4];
        #pragma unroll
        for (int rr = 0; rr < 4; ++rr) {
            float4 hv = *(const float4*)&Hs[ty + rr * 8][f];
            acc[rr][0] += hv.x * w0.x + hv.y * w1.x + hv.z * w2.x + hv.w * w3.x;
            acc[rr][1] += hv.x * w0.y + hv.y * w1.y + hv.z * w2.y + hv.w * w3.y;
            acc[rr][2] += hv.x * w0.z + hv.y * w1.z + hv.z * w2.z + hv.w * w3.z;
            acc[rr][3] += hv.x * w0.w + hv.y * w1.w + hv.z * w2.w + hv.w * w3.w;
        }
    }

    #pragma unroll
    for (int rr = 0; rr < 4; ++rr) {
        int row = r0 + ty + rr * 8;
        if (row < NN) {
            float4 v;
            v.x = elu1(acc[rr][0]);
            v.y = elu1(acc[rr][1]);
            v.z = elu1(acc[rr][2]);
            v.w = elu1(acc[rr][3]);
            *(float4*)&out[row * FF + tx * 4] = v;
        }
    }
}

// ---------------- launch ----------------
extern "C" void kernel_launch(void* const* d_in, const int* in_sizes, int n_in,
                              void* d_out, int out_size) {
    const float* x    = (const float*)d_in[0];
    const int*   erow = (const int*)  d_in[1];
    const int*   ecol = (const int*)  d_in[2];
    const float* aval = (const float*)d_in[3];
    const int*   tid  = (const int*)  d_in[4];
    const float* M    = (const float*)d_in[5];
    const float* W    = (const float*)d_in[6];
    float*       out  = (float*)d_out;

    k_zero   <<<(NN + 255) / 256, 256>>>();
    k_mask   <<<(NT + 255) / 256, 256>>>(tid);
    k_meff   <<<(NN * FF / 4 + 255) / 256, 256>>>(x, M);
    k_hist   <<<(NE + 255) / 256, 256>>>(erow);
    k_scan1  <<<NCHUNK, 1024>>>();
    k_scan2  <<<1, 32>>>();
    k_scan3  <<<(NN + 255) / 256, 256>>>();
    k_scatter<<<(NE + 255) / 256, 256>>>(erow, ecol, aval);
    k_gather <<<(NN * 32 + 255) / 256, 256>>>();
    k_gemm   <<<(NN + 31) / 32, 256>>>(W, out);
}